// round 8
// baseline (speedup 1.0000x reference)
#include <cuda_runtime.h>
#include <cuda_bf16.h>
#include <cstdint>

// Correlation cost volume via bf16 tensor MMA (3-way bf16 split of fp32).
//   out[b,i,h,x] = (1/128) * sum_c L[b,c,h,x] * R[b,c,h,x-i],  x>=i, else 0
// b=8, c=128, h=96, w=320, D=48.
//
// Per (b,h), 128-wide x tile: D[m,n] = sum_k A[m,k]B[n,k],
// A[m,k]=L[k, X+m], B[n,k]=R[k, X-48+n]; out(i, X+m) = D[m, m+48-i]/128.
// fp32 = hi(bf16)+lo(bf16); D += Ah*Bh + Ah*Bl + Al*Bh.
//
// R8: occupancy push. 16-channel chunks (8x), double-buffered 38.9KB smem,
// launch_bounds(256,3) -> 3 CTAs/SM (24 warps). Register prefetch of chunk
// k+1 LDGs across the MMAs of chunk k. Loop-invariant ldmatrix offsets.

namespace {
constexpr int kB = 8, kC = 128, kH = 96, kW = 320, kD = 48;
constexpr int CHW = kH * kW;            // 30720
constexpr int TM = 128;                 // x per CTA tile
constexpr int TN = 176;                 // x' rows staged
constexpr int NT = 256;                 // 8 warps; warp wid owns m16 tile
constexpr int NCHUNK = 8;               // 16 channels per chunk

// row = 32 B (16 bf16) per hi/lo half
constexpr int OFF_AH = 0;               // 128*32 = 4096
constexpr int OFF_AL = 4096;
constexpr int OFF_BH = 8192;            // 176*32 = 5632
constexpr int OFF_BL = 13824;
constexpr int BUFB   = 19456;
constexpr int BNC_PITCH = 81;           // floats per bounce row
constexpr int SMEM_TOTAL = TM * BNC_PITCH * 4;   // 41472 >= 2*BUFB (38912)
}

__device__ __forceinline__ uint32_t smem_u32(const void* p) {
    uint32_t a;
    asm("{ .reg .u64 t; cvta.to.shared.u64 t, %1; cvt.u32.u64 %0, t; }" : "=r"(a) : "l"(p));
    return a;
}
__device__ __forceinline__ void ldsm_x4(uint32_t* r, uint32_t addr) {
    asm volatile("ldmatrix.sync.aligned.m8n8.x4.shared.b16 {%0,%1,%2,%3}, [%4];"
                 : "=r"(r[0]), "=r"(r[1]), "=r"(r[2]), "=r"(r[3]) : "r"(addr));
}
__device__ __forceinline__ void mma_bf16(float* d, const uint32_t* a, const uint32_t* b) {
    asm volatile(
        "mma.sync.aligned.m16n8k16.row.col.f32.bf16.bf16.f32 "
        "{%0,%1,%2,%3}, {%4,%5,%6,%7}, {%8,%9}, {%0,%1,%2,%3};"
        : "+f"(d[0]), "+f"(d[1]), "+f"(d[2]), "+f"(d[3])
        : "r"(a[0]), "r"(a[1]), "r"(a[2]), "r"(a[3]), "r"(b[0]), "r"(b[1]));
}
__device__ __forceinline__ void mma3(float* d, const uint32_t* ah, const uint32_t* al,
                                     const uint32_t* bh, const uint32_t* bl) {
    mma_bf16(d, ah, bh);
    mma_bf16(d, ah, bl);
    mma_bf16(d, al, bh);
}

// fp32x4 -> hi bf16x4 packed + residuals
__device__ __forceinline__ uint2 split_hi(float f0, float f1, float f2, float f3,
                                          float& r0, float& r1, float& r2, float& r3) {
    __nv_bfloat162 a = __floats2bfloat162_rn(f0, f1);
    __nv_bfloat162 b = __floats2bfloat162_rn(f2, f3);
    r0 = f0 - __bfloat162float(a.x);
    r1 = f1 - __bfloat162float(a.y);
    r2 = f2 - __bfloat162float(b.x);
    r3 = f3 - __bfloat162float(b.y);
    uint2 v;
    v.x = *reinterpret_cast<uint32_t*>(&a);
    v.y = *reinterpret_cast<uint32_t*>(&b);
    return v;
}
__device__ __forceinline__ uint2 pack_lo(float r0, float r1, float r2, float r3) {
    __nv_bfloat162 a = __floats2bfloat162_rn(r0, r1);
    __nv_bfloat162 b = __floats2bfloat162_rn(r2, r3);
    uint2 v;
    v.x = *reinterpret_cast<uint32_t*>(&a);
    v.y = *reinterpret_cast<uint32_t*>(&b);
    return v;
}

// pitch-32 swizzle: 16B line ^= (row>>2)&1 -> any 8 consecutive rows (fixed
// line) occupy 8 distinct 16B slots mod 8 (CF for STS.128 and ldmatrix).
__device__ __forceinline__ uint32_t swoff(uint32_t row, uint32_t line) {
    return row * 32u + ((line ^ ((row >> 2) & 1u)) << 4);
}

extern __shared__ char smem[];

__global__ __launch_bounds__(NT, 3)
void costvol_occ(const float* __restrict__ L, const float* __restrict__ R,
                 float* __restrict__ out) {
    const uint32_t sb = smem_u32(smem);
    const int tid = threadIdx.x;
    const int wid = tid >> 5;
    const int lid = tid & 31;

    const int tile = blockIdx.x;            // 0..2
    const int bh   = blockIdx.y;            // 0..767
    const int b = bh / kH;
    const int h = bh - b * kH;
    const int X = tile * TM;

    // ---- staging slot geometry (per thread, per 16-ch chunk) ----
    // A: 256 slots (128 rows x 2 g8): slot = tid.
    // B: 352 slots (176 rows x 2 g8): slot0 = tid, slot1 = tid+256 (tid<96).
    const int rowAs = tid & 127, g8A = tid >> 7;
    const int g8B0 = (tid < 176) ? 0 : 1;
    const int rowB0 = tid - g8B0 * 176;
    const int rowB1 = tid + 80;             // slot tid+256 -> g8=1, row=tid+80
    const bool vB1 = (tid < 96);

    const bool okA = (X + rowAs) < kW;
    const int xpB0 = X - kD + rowB0;  const bool okB0 = (xpB0 >= 0) && (xpB0 < kW);
    const int xpB1 = X - kD + rowB1;  const bool okB1 = vB1 && (xpB1 >= 0) && (xpB1 < kW);

    const float* Lb = L + ((long)(b * kC) * kH + h) * kW;
    const float* Rb = R + ((long)(b * kC) * kH + h) * kW;
    const float* pA0  = Lb + (long)(8 * g8A) * CHW + X + rowAs;
    const float* pB0b = Rb + (okB0 ? xpB0 : 0);
    if (g8B0) pB0b += (long)8 * CHW;
    const float* pB1b = Rb + (long)8 * CHW + (okB1 ? xpB1 : 0);

    float fA[8], fB0[8], fB1[8];

    auto loads = [&](int k) {
        const long co = (long)(16 * k) * CHW;
#pragma unroll
        for (int j = 0; j < 8; j++) {
            fA[j]  = okA  ? pA0 [co + j * CHW] : 0.f;
            fB0[j] = okB0 ? pB0b[co + j * CHW] : 0.f;
            fB1[j] = okB1 ? pB1b[co + j * CHW] : 0.f;
        }
    };

    auto cvt_store = [&](const float* f, int off_hi, int off_lo, int row, int g8) {
        float r[8];
        const uint2 h0 = split_hi(f[0], f[1], f[2], f[3], r[0], r[1], r[2], r[3]);
        const uint2 h1 = split_hi(f[4], f[5], f[6], f[7], r[4], r[5], r[6], r[7]);
        const uint2 l0 = pack_lo(r[0], r[1], r[2], r[3]);
        const uint2 l1 = pack_lo(r[4], r[5], r[6], r[7]);
        const uint32_t off = swoff((uint32_t)row, (uint32_t)g8);
        uint4 hv; hv.x = h0.x; hv.y = h0.y; hv.z = h1.x; hv.w = h1.y;
        uint4 lv; lv.x = l0.x; lv.y = l0.y; lv.z = l1.x; lv.w = l1.y;
        *reinterpret_cast<uint4*>(smem + off_hi + off) = hv;
        *reinterpret_cast<uint4*>(smem + off_lo + off) = lv;
    };

    auto stage = [&](int buf) {
        const int bo = buf * BUFB;
        cvt_store(fA,  bo + OFF_AH, bo + OFF_AL, rowAs, g8A);
        cvt_store(fB0, bo + OFF_BH, bo + OFF_BL, rowB0, g8B0);
        if (vB1) cvt_store(fB1, bo + OFF_BH, bo + OFF_BL, rowB1, 1);
    };

    // ---- consumer: warp wid owns m rows [16wid,16wid+16), 64-row B window
    float acc[8][4];
#pragma unroll
    for (int j = 0; j < 8; j++)
#pragma unroll
        for (int q = 0; q < 4; q++) acc[j][q] = 0.f;

    const uint32_t rowA = 16u * wid + (lid & 15);
    const uint32_t aHalf = (uint32_t)(lid >> 4);
    const uint32_t bRow  = 8u * (uint32_t)(lid >> 4) + (lid & 7);
    const uint32_t bHalf = (uint32_t)((lid >> 3) & 1);

    // loop-invariant ldmatrix offsets
    const uint32_t aoff = swoff(rowA, aHalf);
    uint32_t boff[4];
#pragma unroll
    for (int jp = 0; jp < 4; jp++)
        boff[jp] = swoff(16u * wid + 16u * jp + bRow, bHalf);

    auto domma = [&](int buf) {
        const uint32_t base = sb + buf * BUFB;
        uint32_t ah[4], al[4];
        ldsm_x4(ah, base + OFF_AH + aoff);
        ldsm_x4(al, base + OFF_AL + aoff);
#pragma unroll
        for (int jp = 0; jp < 4; jp++) {
            uint32_t bh4[4], bl4[4];
            ldsm_x4(bh4, base + OFF_BH + boff[jp]);
            ldsm_x4(bl4, base + OFF_BL + boff[jp]);
            mma3(acc[2 * jp],     ah, al, bh4,     bl4);
            mma3(acc[2 * jp + 1], ah, al, bh4 + 2, bl4 + 2);
        }
    };

    // ---- pipeline: LDG(k+1) in flight across MMA(k); convert/store after ----
    loads(0);
    stage(0);
    __syncthreads();
#pragma unroll 2
    for (int k = 0; k < NCHUNK; k++) {
        if (k + 1 < NCHUNK) loads(k + 1);
        domma(k & 1);
        if (k + 1 < NCHUNK) stage((k + 1) & 1);
        __syncthreads();
    }

    // ---- acc -> bounce (scaled): warp wid rows [16wid,16wid+16), 64 cols ----
    {
        float* bnc = reinterpret_cast<float*>(smem);
        const float sc = 1.0f / (float)kC;
        const int q = lid >> 2;
        const int e = lid & 3;
        const int m0 = 16 * wid + q;
#pragma unroll
        for (int j = 0; j < 8; j++) {
            const int col = 8 * j + 2 * e;
            bnc[m0 * BNC_PITCH + col]           = acc[j][0] * sc;
            bnc[m0 * BNC_PITCH + col + 1]       = acc[j][1] * sc;
            bnc[(m0 + 8) * BNC_PITCH + col]     = acc[j][2] * sc;
            bnc[(m0 + 8) * BNC_PITCH + col + 1] = acc[j][3] * sc;
        }
    }
    __syncthreads();

    // ---- out[b,i,h,X+xl] = bounce[xl][(xl&15) + 48 - i], coalesced in x ----
    const int xl = tid & 127;
    if (X + xl < kW) {
        const float* bnr = reinterpret_cast<const float*>(smem)
                         + xl * BNC_PITCH + (xl & 15) + 48;
        float* ob = out + (long)(b * kD) * CHW + h * kW + X + xl;
#pragma unroll
        for (int it = 0; it < 24; it++) {
            const int i = 2 * it + (tid >> 7);
            ob[(long)i * CHW] = bnr[-i];
        }
    }
}

extern "C" void kernel_launch(void* const* d_in, const int* in_sizes, int n_in,
                              void* d_out, int out_size) {
    const float* L = (const float*)d_in[0];
    const float* R = (const float*)d_in[1];
    float* out = (float*)d_out;

    cudaFuncSetAttribute(costvol_occ,
                         cudaFuncAttributeMaxDynamicSharedMemorySize, SMEM_TOTAL);

    dim3 grid((kW + TM - 1) / TM, kB * kH);   // (3, 768) = 2304 CTAs
    costvol_occ<<<grid, NT, SMEM_TOTAL>>>(L, R, out);
}

// round 9
// speedup vs baseline: 1.4553x; 1.4553x over previous
#include <cuda_runtime.h>
#include <cuda_bf16.h>
#include <cstdint>

// Correlation cost volume via bf16 tensor MMA (3-way bf16 split of fp32).
//   out[b,i,h,x] = (1/128) * sum_c L[b,c,h,x] * R[b,c,h,x-i],  x>=i, else 0
// b=8, c=128, h=96, w=320, D=48.
//
// R9: R7 pipeline (32-ch chunks, double buffer, register prefetch) with
// TM=160 (320 = 2 exact tiles -> no OOB tile waste) and NT=320 (10 warps,
// m16 each), launch_bounds(320,2) -> 20 warps/SM.

namespace {
constexpr int kB = 8, kC = 128, kH = 96, kW = 320, kD = 48;
constexpr int CHW = kH * kW;            // 30720
constexpr int TM = 160;                 // x per CTA tile (2 exact tiles)
constexpr int TN = TM + kD;             // 208 x' rows staged
constexpr int NT = 320;                 // 10 warps; warp wid owns m16 tile
constexpr int NCHUNK = 4;               // 32 channels per chunk

// row = 64 B (32 bf16) per hi/lo half
constexpr int A_HALF = TM * 64;         // 10240
constexpr int B_HALF = TN * 64;         // 13312
constexpr int OFF_AH = 0;
constexpr int OFF_AL = A_HALF;          // 10240
constexpr int OFF_BH = 2 * A_HALF;      // 20480
constexpr int OFF_BL = OFF_BH + B_HALF; // 33792
constexpr int BUFB   = OFF_BL + B_HALF; // 47104
constexpr int SMEM_TOTAL = 2 * BUFB;    // 94208; bounce (51840) overlays
constexpr int BNC_PITCH = 81;           // floats per bounce row
}

__device__ __forceinline__ uint32_t smem_u32(const void* p) {
    uint32_t a;
    asm("{ .reg .u64 t; cvta.to.shared.u64 t, %1; cvt.u32.u64 %0, t; }" : "=r"(a) : "l"(p));
    return a;
}
__device__ __forceinline__ void ldsm_x4(uint32_t* r, uint32_t addr) {
    asm volatile("ldmatrix.sync.aligned.m8n8.x4.shared.b16 {%0,%1,%2,%3}, [%4];"
                 : "=r"(r[0]), "=r"(r[1]), "=r"(r[2]), "=r"(r[3]) : "r"(addr));
}
__device__ __forceinline__ void mma_bf16(float* d, const uint32_t* a, const uint32_t* b) {
    asm volatile(
        "mma.sync.aligned.m16n8k16.row.col.f32.bf16.bf16.f32 "
        "{%0,%1,%2,%3}, {%4,%5,%6,%7}, {%8,%9}, {%0,%1,%2,%3};"
        : "+f"(d[0]), "+f"(d[1]), "+f"(d[2]), "+f"(d[3])
        : "r"(a[0]), "r"(a[1]), "r"(a[2]), "r"(a[3]), "r"(b[0]), "r"(b[1]));
}
__device__ __forceinline__ void mma3(float* d, const uint32_t* ah, const uint32_t* al,
                                     const uint32_t* bh, const uint32_t* bl) {
    mma_bf16(d, ah, bh);
    mma_bf16(d, ah, bl);
    mma_bf16(d, al, bh);
}

// fp32x4 -> hi bf16x4 packed + residuals
__device__ __forceinline__ uint2 split_hi(float f0, float f1, float f2, float f3,
                                          float& r0, float& r1, float& r2, float& r3) {
    __nv_bfloat162 a = __floats2bfloat162_rn(f0, f1);
    __nv_bfloat162 b = __floats2bfloat162_rn(f2, f3);
    r0 = f0 - __bfloat162float(a.x);
    r1 = f1 - __bfloat162float(a.y);
    r2 = f2 - __bfloat162float(b.x);
    r3 = f3 - __bfloat162float(b.y);
    uint2 v;
    v.x = *reinterpret_cast<uint32_t*>(&a);
    v.y = *reinterpret_cast<uint32_t*>(&b);
    return v;
}
__device__ __forceinline__ uint2 pack_lo(float r0, float r1, float r2, float r3) {
    __nv_bfloat162 a = __floats2bfloat162_rn(r0, r1);
    __nv_bfloat162 b = __floats2bfloat162_rn(r2, r3);
    uint2 v;
    v.x = *reinterpret_cast<uint32_t*>(&a);
    v.y = *reinterpret_cast<uint32_t*>(&b);
    return v;
}

// pitch-64 swizzle: 16B line ^= (row>>1)&3 -> any 8 consecutive rows hit 8
// distinct 16B slots per 128B (CF for STS.128 and all ldmatrix phases).
__device__ __forceinline__ uint32_t swoff(uint32_t row, uint32_t line) {
    return row * 64u + ((line ^ ((row >> 1) & 3u)) << 4);
}

extern __shared__ char smem[];

__global__ __launch_bounds__(NT, 2)
void costvol_t160(const float* __restrict__ L, const float* __restrict__ R,
                  float* __restrict__ out) {
    const uint32_t sb = smem_u32(smem);
    const int tid = threadIdx.x;
    const int wid = tid >> 5;
    const int lid = tid & 31;

    const int tile = blockIdx.x;            // 0..1
    const int bh   = blockIdx.y;            // 0..767
    const int b = bh / kH;
    const int h = bh - b * kH;
    const int X = tile * TM;

    // ---- staging slot geometry (per thread, per 32-ch chunk) ----
    // A: 640 slots (160 rows x 4 g8): s0 = tid (g8 in {0,1}), s1 = tid+320 (g8+2).
    // B: 832 slots (208 rows x 4 g8): s0 = tid, s1 = tid+320, s2 = tid+640 (tid<192).
    const int g8A   = tid / TM;              // 0 or 1
    const int rowAs = tid - g8A * TM;        // same row for both A slots

    const int g8B0 = tid / TN;               // 0 or 1
    const int rowB0 = tid - g8B0 * TN;
    const int g8B1 = (tid + NT) / TN;        // 1, 2 or 3
    const int rowB1 = tid + NT - g8B1 * TN;
    const int rowB2 = tid + 16;              // slot tid+640 -> g8 = 3
    const bool vB2 = (tid < 2 * TN + 16 - NT + 160);  // tid < 192
    // (832 - 640 = 192 slots in the third pass)

    const int xpB0 = X - kD + rowB0;  const bool okB0 = (xpB0 >= 0);
    const int xpB1 = X - kD + rowB1;  const bool okB1 = (xpB1 >= 0);
    const int xpB2 = X - kD + rowB2;  const bool okB2 = (tid < 192) && (xpB2 >= 0);

    const float* Lb = L + ((long)(b * kC) * kH + h) * kW;
    const float* Rb = R + ((long)(b * kC) * kH + h) * kW;
    const float* pA0  = Lb + (long)(8 * g8A) * CHW + X + rowAs;        // g8A
    const float* pA1  = pA0 + (long)16 * CHW;                          // g8A+2
    const float* pB0b = Rb + (long)(8 * g8B0) * CHW + (okB0 ? xpB0 : 0);
    const float* pB1b = Rb + (long)(8 * g8B1) * CHW + (okB1 ? xpB1 : 0);
    const float* pB2b = Rb + (long)(8 * 3)    * CHW + (okB2 ? xpB2 : 0);

    float fA0[8], fA1[8], fB0[8], fB1[8], fB2[8];

    auto loads = [&](int k) {
        const long co = (long)(32 * k) * CHW;
#pragma unroll
        for (int j = 0; j < 8; j++) {
            fA0[j] = pA0[co + j * CHW];
            fA1[j] = pA1[co + j * CHW];
            fB0[j] = okB0 ? pB0b[co + j * CHW] : 0.f;
            fB1[j] = okB1 ? pB1b[co + j * CHW] : 0.f;
            fB2[j] = okB2 ? pB2b[co + j * CHW] : 0.f;
        }
    };

    auto cvt_store = [&](const float* f, int off_hi, int off_lo, int row, int g8) {
        float r[8];
        const uint2 h0 = split_hi(f[0], f[1], f[2], f[3], r[0], r[1], r[2], r[3]);
        const uint2 h1 = split_hi(f[4], f[5], f[6], f[7], r[4], r[5], r[6], r[7]);
        const uint2 l0 = pack_lo(r[0], r[1], r[2], r[3]);
        const uint2 l1 = pack_lo(r[4], r[5], r[6], r[7]);
        const uint32_t off = swoff((uint32_t)row, (uint32_t)g8);
        uint4 hv; hv.x = h0.x; hv.y = h0.y; hv.z = h1.x; hv.w = h1.y;
        uint4 lv; lv.x = l0.x; lv.y = l0.y; lv.z = l1.x; lv.w = l1.y;
        *reinterpret_cast<uint4*>(smem + off_hi + off) = hv;
        *reinterpret_cast<uint4*>(smem + off_lo + off) = lv;
    };

    auto stage = [&](int buf) {
        const int bo = buf * BUFB;
        cvt_store(fA0, bo + OFF_AH, bo + OFF_AL, rowAs, g8A);
        cvt_store(fA1, bo + OFF_AH, bo + OFF_AL, rowAs, g8A + 2);
        cvt_store(fB0, bo + OFF_BH, bo + OFF_BL, rowB0, g8B0);
        cvt_store(fB1, bo + OFF_BH, bo + OFF_BL, rowB1, g8B1);
        if (tid < 192) cvt_store(fB2, bo + OFF_BH, bo + OFF_BL, rowB2, 3);
    };

    // ---- consumer: warp wid owns m rows [16wid,16wid+16), 64-row B window
    float acc[8][4];
#pragma unroll
    for (int j = 0; j < 8; j++)
#pragma unroll
        for (int q = 0; q < 4; q++) acc[j][q] = 0.f;

    const uint32_t rowA = 16u * wid + (lid & 15);
    const uint32_t aHalf = (uint32_t)(lid >> 4);
    const uint32_t bRow  = 8u * (uint32_t)(lid >> 4) + (lid & 7);
    const uint32_t bHalf = (uint32_t)((lid >> 3) & 1);

    auto domma = [&](int buf) {
        const uint32_t base = sb + buf * BUFB;
#pragma unroll
        for (int ks = 0; ks < 2; ks++) {
            uint32_t ah[4], al[4];
            const uint32_t aoff = swoff(rowA, 2u * ks + aHalf);
            ldsm_x4(ah, base + OFF_AH + aoff);
            ldsm_x4(al, base + OFF_AL + aoff);
#pragma unroll
            for (int jp = 0; jp < 4; jp++) {
                uint32_t bh4[4], bl4[4];
                const uint32_t boff = swoff(16u * wid + 16u * jp + bRow, 2u * ks + bHalf);
                ldsm_x4(bh4, base + OFF_BH + boff);
                ldsm_x4(bl4, base + OFF_BL + boff);
                mma3(acc[2 * jp],     ah, al, bh4,     bl4);
                mma3(acc[2 * jp + 1], ah, al, bh4 + 2, bl4 + 2);
            }
        }
    };

    // ---- pipeline: LDG(k+1) in flight across MMA(k); convert/store after ----
    loads(0);
    stage(0);
    __syncthreads();
#pragma unroll
    for (int k = 0; k < NCHUNK; k++) {
        if (k + 1 < NCHUNK) loads(k + 1);
        domma(k & 1);
        if (k + 1 < NCHUNK) stage((k + 1) & 1);
        __syncthreads();
    }

    // ---- acc -> bounce (scaled): warp wid rows [16wid,16wid+16), 64 cols ----
    {
        float* bnc = reinterpret_cast<float*>(smem);
        const float sc = 1.0f / (float)kC;
        const int q = lid >> 2;
        const int e = lid & 3;
        const int m0 = 16 * wid + q;
#pragma unroll
        for (int j = 0; j < 8; j++) {
            const int col = 8 * j + 2 * e;
            bnc[m0 * BNC_PITCH + col]           = acc[j][0] * sc;
            bnc[m0 * BNC_PITCH + col + 1]       = acc[j][1] * sc;
            bnc[(m0 + 8) * BNC_PITCH + col]     = acc[j][2] * sc;
            bnc[(m0 + 8) * BNC_PITCH + col + 1] = acc[j][3] * sc;
        }
    }
    __syncthreads();

    // ---- out[b,i,h,X+xl] = bounce[xl][(xl&15) + 48 - i], coalesced in x ----
    {
        const int half = tid / TM;               // 0 or 1
        const int xl   = tid - half * TM;        // 0..159
        const float* bnr = reinterpret_cast<const float*>(smem)
                         + xl * BNC_PITCH + (xl & 15) + 48;
        float* ob = out + (long)(b * kD) * CHW + h * kW + X + xl;
#pragma unroll
        for (int it = 0; it < 24; it++) {
            const int i = 2 * it + half;
            ob[(long)i * CHW] = bnr[-i];
        }
    }
}

extern "C" void kernel_launch(void* const* d_in, const int* in_sizes, int n_in,
                              void* d_out, int out_size) {
    const float* L = (const float*)d_in[0];
    const float* R = (const float*)d_in[1];
    float* out = (float*)d_out;

    cudaFuncSetAttribute(costvol_t160,
                         cudaFuncAttributeMaxDynamicSharedMemorySize, SMEM_TOTAL);

    dim3 grid(kW / TM, kB * kH);   // (2, 768) = 1536 CTAs
    costvol_t160<<<grid, NT, SMEM_TOTAL>>>(L, R, out);
}

// round 10
// speedup vs baseline: 1.6953x; 1.1650x over previous
#include <cuda_runtime.h>
#include <cuda_fp16.h>
#include <cstdint>

// Correlation cost volume via single-pass fp16 tensor MMA (fp32 accumulate).
//   out[b,i,h,x] = (1/128) * sum_c L[b,c,h,x] * R[b,c,h,x-i],  x>=i, else 0
// b=8, c=128, h=96, w=320, D=48.
//
// R10: drop the bf16 3-way split. fp16 rn rounding of N(0,1) inputs gives
// aggregate rel_err ~4e-4 (<1e-3 threshold); tensor passes 3->1, staged
// bytes/STS/LDSM halve. R9 skeleton retained: TM=160 (2 exact tiles),
// NT=320 (10 warps, m16 each), 32-ch chunks, double buffer, register
// prefetch of chunk k+1 LDGs across MMA(k).

namespace {
constexpr int kB = 8, kC = 128, kH = 96, kW = 320, kD = 48;
constexpr int CHW = kH * kW;            // 30720
constexpr int TM = 160;                 // x per CTA tile
constexpr int TN = TM + kD;             // 208 x' rows staged
constexpr int NT = 320;                 // 10 warps; warp wid owns m16 tile
constexpr int NCHUNK = 4;               // 32 channels per chunk

// row = 64 B (32 fp16) per chunk
constexpr int OFF_A = 0;                // 160*64 = 10240
constexpr int OFF_B = TM * 64;          // 10240; B: 208*64 = 13312
constexpr int BUFB  = OFF_B + TN * 64;  // 23552
constexpr int BNC_PITCH = 81;           // floats per bounce row
constexpr int SMEM_TOTAL = TM * BNC_PITCH * 4;   // 51840 > 2*BUFB (47104)
}

__device__ __forceinline__ uint32_t smem_u32(const void* p) {
    uint32_t a;
    asm("{ .reg .u64 t; cvta.to.shared.u64 t, %1; cvt.u32.u64 %0, t; }" : "=r"(a) : "l"(p));
    return a;
}
__device__ __forceinline__ void ldsm_x4(uint32_t* r, uint32_t addr) {
    asm volatile("ldmatrix.sync.aligned.m8n8.x4.shared.b16 {%0,%1,%2,%3}, [%4];"
                 : "=r"(r[0]), "=r"(r[1]), "=r"(r[2]), "=r"(r[3]) : "r"(addr));
}
__device__ __forceinline__ void mma_f16(float* d, const uint32_t* a, const uint32_t* b) {
    asm volatile(
        "mma.sync.aligned.m16n8k16.row.col.f32.f16.f16.f32 "
        "{%0,%1,%2,%3}, {%4,%5,%6,%7}, {%8,%9}, {%0,%1,%2,%3};"
        : "+f"(d[0]), "+f"(d[1]), "+f"(d[2]), "+f"(d[3])
        : "r"(a[0]), "r"(a[1]), "r"(a[2]), "r"(a[3]), "r"(b[0]), "r"(b[1]));
}

// pitch-64 swizzle: 16B line ^= (row>>1)&3 -> any 8 consecutive rows hit 8
// distinct 16B slots per 128B (CF for STS.128 and all ldmatrix phases).
__device__ __forceinline__ uint32_t swoff(uint32_t row, uint32_t line) {
    return row * 64u + ((line ^ ((row >> 1) & 3u)) << 4);
}

extern __shared__ char smem[];

__global__ __launch_bounds__(NT, 2)
void costvol_h1(const float* __restrict__ L, const float* __restrict__ R,
                float* __restrict__ out) {
    const uint32_t sb = smem_u32(smem);
    const int tid = threadIdx.x;
    const int wid = tid >> 5;
    const int lid = tid & 31;

    const int tile = blockIdx.x;            // 0..1
    const int bh   = blockIdx.y;            // 0..767
    const int b = bh / kH;
    const int h = bh - b * kH;
    const int X = tile * TM;

    // ---- staging slot geometry (per thread, per 32-ch chunk) ----
    // A: 640 slots (160 rows x 4 g8): s0 = tid, s1 = tid+320.
    // B: 832 slots (208 rows x 4 g8): s0 = tid, s1 = tid+320, s2 = tid+640 (tid<192).
    const int g8A   = tid / TM;              // 0 or 1 (slot1 adds +2)
    const int rowAs = tid - g8A * TM;

    const int g8B0 = tid / TN;               // 0 or 1
    const int rowB0 = tid - g8B0 * TN;
    const int g8B1 = (tid + NT) / TN;        // 1, 2 or 3
    const int rowB1 = tid + NT - g8B1 * TN;
    const int rowB2 = tid + 16;              // slot tid+640 -> g8 = 3

    const int xpB0 = X - kD + rowB0;  const bool okB0 = (xpB0 >= 0);
    const int xpB1 = X - kD + rowB1;  const bool okB1 = (xpB1 >= 0);
    const int xpB2 = X - kD + rowB2;  const bool okB2 = (tid < 192) && (xpB2 >= 0);

    const float* Lb = L + ((long)(b * kC) * kH + h) * kW;
    const float* Rb = R + ((long)(b * kC) * kH + h) * kW;
    const float* pA0  = Lb + (long)(8 * g8A) * CHW + X + rowAs;        // g8A
    const float* pA1  = pA0 + (long)16 * CHW;                          // g8A+2
    const float* pB0b = Rb + (long)(8 * g8B0) * CHW + (okB0 ? xpB0 : 0);
    const float* pB1b = Rb + (long)(8 * g8B1) * CHW + (okB1 ? xpB1 : 0);
    const float* pB2b = Rb + (long)(8 * 3)    * CHW + (okB2 ? xpB2 : 0);

    float fA0[8], fA1[8], fB0[8], fB1[8], fB2[8];

    auto loads = [&](int k) {
        const long co = (long)(32 * k) * CHW;
#pragma unroll
        for (int j = 0; j < 8; j++) {
            fA0[j] = pA0[co + j * CHW];
            fA1[j] = pA1[co + j * CHW];
            fB0[j] = okB0 ? pB0b[co + j * CHW] : 0.f;
            fB1[j] = okB1 ? pB1b[co + j * CHW] : 0.f;
            fB2[j] = okB2 ? pB2b[co + j * CHW] : 0.f;
        }
    };

    auto cvt_store = [&](const float* f, int base_off, int row, int g8) {
        __half2 p0 = __floats2half2_rn(f[0], f[1]);
        __half2 p1 = __floats2half2_rn(f[2], f[3]);
        __half2 p2 = __floats2half2_rn(f[4], f[5]);
        __half2 p3 = __floats2half2_rn(f[6], f[7]);
        uint4 v;
        v.x = *reinterpret_cast<uint32_t*>(&p0);
        v.y = *reinterpret_cast<uint32_t*>(&p1);
        v.z = *reinterpret_cast<uint32_t*>(&p2);
        v.w = *reinterpret_cast<uint32_t*>(&p3);
        *reinterpret_cast<uint4*>(smem + base_off + swoff((uint32_t)row, (uint32_t)g8)) = v;
    };

    auto stage = [&](int buf) {
        const int bo = buf * BUFB;
        cvt_store(fA0, bo + OFF_A, rowAs, g8A);
        cvt_store(fA1, bo + OFF_A, rowAs, g8A + 2);
        cvt_store(fB0, bo + OFF_B, rowB0, g8B0);
        cvt_store(fB1, bo + OFF_B, rowB1, g8B1);
        if (tid < 192) cvt_store(fB2, bo + OFF_B, rowB2, 3);
    };

    // ---- consumer: warp wid owns m rows [16wid,16wid+16), 64-row B window
    float acc[8][4];
#pragma unroll
    for (int j = 0; j < 8; j++)
#pragma unroll
        for (int q = 0; q < 4; q++) acc[j][q] = 0.f;

    const uint32_t rowA = 16u * wid + (lid & 15);
    const uint32_t aHalf = (uint32_t)(lid >> 4);
    const uint32_t bRow  = 8u * (uint32_t)(lid >> 4) + (lid & 7);
    const uint32_t bHalf = (uint32_t)((lid >> 3) & 1);

    auto domma = [&](int buf) {
        const uint32_t base = sb + buf * BUFB;
#pragma unroll
        for (int ks = 0; ks < 2; ks++) {
            uint32_t a4[4];
            ldsm_x4(a4, base + OFF_A + swoff(rowA, 2u * ks + aHalf));
#pragma unroll
            for (int jp = 0; jp < 4; jp++) {
                uint32_t b4[4];
                ldsm_x4(b4, base + OFF_B
                            + swoff(16u * wid + 16u * jp + bRow, 2u * ks + bHalf));
                mma_f16(acc[2 * jp],     a4, b4);
                mma_f16(acc[2 * jp + 1], a4, b4 + 2);
            }
        }
    };

    // ---- pipeline: LDG(k+1) in flight across MMA(k); convert/store after ----
    loads(0);
    stage(0);
    __syncthreads();
#pragma unroll
    for (int k = 0; k < NCHUNK; k++) {
        if (k + 1 < NCHUNK) loads(k + 1);
        domma(k & 1);
        if (k + 1 < NCHUNK) stage((k + 1) & 1);
        __syncthreads();
    }

    // ---- acc -> bounce (scaled): warp wid rows [16wid,16wid+16), 64 cols ----
    {
        float* bnc = reinterpret_cast<float*>(smem);
        const float sc = 1.0f / (float)kC;
        const int q = lid >> 2;
        const int e = lid & 3;
        const int m0 = 16 * wid + q;
#pragma unroll
        for (int j = 0; j < 8; j++) {
            const int col = 8 * j + 2 * e;
            bnc[m0 * BNC_PITCH + col]           = acc[j][0] * sc;
            bnc[m0 * BNC_PITCH + col + 1]       = acc[j][1] * sc;
            bnc[(m0 + 8) * BNC_PITCH + col]     = acc[j][2] * sc;
            bnc[(m0 + 8) * BNC_PITCH + col + 1] = acc[j][3] * sc;
        }
    }
    __syncthreads();

    // ---- out[b,i,h,X+xl] = bounce[xl][(xl&15) + 48 - i], coalesced in x ----
    {
        const int half = tid / TM;               // 0 or 1
        const int xl   = tid - half * TM;        // 0..159
        const float* bnr = reinterpret_cast<const float*>(smem)
                         + xl * BNC_PITCH + (xl & 15) + 48;
        float* ob = out + (long)(b * kD) * CHW + h * kW + X + xl;
#pragma unroll
        for (int it = 0; it < 24; it++) {
            const int i = 2 * it + half;
            ob[(long)i * CHW] = bnr[-i];
        }
    }
}

extern "C" void kernel_launch(void* const* d_in, const int* in_sizes, int n_in,
                              void* d_out, int out_size) {
    const float* L = (const float*)d_in[0];
    const float* R = (const float*)d_in[1];
    float* out = (float*)d_out;

    cudaFuncSetAttribute(costvol_h1,
                         cudaFuncAttributeMaxDynamicSharedMemorySize, SMEM_TOTAL);

    dim3 grid(kW / TM, kB * kH);   // (2, 768) = 1536 CTAs
    costvol_h1<<<grid, NT, SMEM_TOTAL>>>(L, R, out);
}